// round 15
// baseline (speedup 1.0000x reference)
#include <cuda_runtime.h>
#include <cuda_bf16.h>

#define A_N   49104
#define B_N   8
#define C_N   80
#define M_N   64
#define TPB   256
#define XBLK  ((A_N + TPB - 1) / TPB)   /* 192 */
#define NBLK  (XBLK * B_N)              /* 1536 */
#define NWARP (TPB/32)

typedef unsigned long long u64t;

// Per-block partials (fully overwritten each launch before being read)
__device__ float    p_cls[NBLK];
__device__ float    p_reg[NBLK];
__device__ int      p_np[NBLK];
__device__ unsigned g_done = 0;         // reset by last block each launch

// ---------------- packed f32x2 helpers (Blackwell) ----------------
__device__ __forceinline__ u64t pk2(float a, float b) {
    u64t r; asm("mov.b64 %0, {%1, %2};" : "=l"(r) : "f"(a), "f"(b)); return r;
}
__device__ __forceinline__ void upk2(u64t v, float& a, float& b) {
    asm("mov.b64 {%0, %1}, %2;" : "=f"(a), "=f"(b) : "l"(v));
}
__device__ __forceinline__ u64t fma2(u64t a, u64t b, u64t c) {
    u64t d; asm("fma.rn.f32x2 %0, %1, %2, %3;" : "=l"(d) : "l"(a), "l"(b), "l"(c)); return d;
}
__device__ __forceinline__ u64t mul2(u64t a, u64t b) {
    u64t d; asm("mul.rn.f32x2 %0, %1, %2;" : "=l"(d) : "l"(a), "l"(b)); return d;
}
#define NEG1P 0xbf800000bf800000ull   /* (-1.f, -1.f) */
#define ONE1P 0x3f8000003f800000ull   /* ( 1.f,  1.f) */

__device__ __forceinline__ float rcp_fast(float x) {
    float y; asm("rcp.approx.f32 %0, %1;" : "=f"(y) : "f"(x)); return y;
}
__device__ __forceinline__ float smooth_l1(float d) {
    return (d <= (1.0f/9.0f)) ? 4.5f * d * d : d - (0.5f/9.0f);
}
__device__ __forceinline__ float bt(float p) {           // p^2*log2(1-p)
    return p * p * __log2f(1.0f - p);
}
__device__ __forceinline__ float pt(float p) {           // 0.25*(1-p)^2*log2(p)
    float q = 1.0f - p;
    return 0.25f * q * q * __log2f(p);
}
// Packed hot quad: sum of p^2*log2(1-p) over 4 elems (R13's proven fastest form)
__device__ __forceinline__ float bt4p(float4 v) {
    u64t v01 = pk2(v.x, v.y);
    u64t v23 = pk2(v.z, v.w);
    u64t q01 = fma2(v01, NEG1P, ONE1P);   // (1-p0, 1-p1)
    u64t q23 = fma2(v23, NEG1P, ONE1P);
    u64t s01 = mul2(v01, v01);            // (p0^2, p1^2)
    u64t s23 = mul2(v23, v23);
    float qa, qb, qc, qd, sa, sb, sc, sd;
    upk2(q01, qa, qb); upk2(q23, qc, qd);
    upk2(s01, sa, sb); upk2(s23, sc, sd);
    float l0 = __log2f(qa), l1 = __log2f(qb), l2 = __log2f(qc), l3 = __log2f(qd);
    float t  = sa * l0;
    t = fmaf(sb, l1, t);
    t = fmaf(sc, l2, t);
    t = fmaf(sd, l3, t);
    return t;
}

__global__ __launch_bounds__(TPB) void fl_main_kernel(
    const float* __restrict__ reg,    // [B, A, 4]
    const float* __restrict__ cls,    // [B, A, C]
    const float* __restrict__ anc,    // [1, A, 4]
    const float* __restrict__ gt,     // [B, M, 5]
    float* __restrict__ out)          // [2]
{
    __shared__ float4 s_gbox[M_N];
    __shared__ float  s_garea[M_N];
    __shared__ int    s_gcls[M_N];
    __shared__ float  s_flag[TPB];    // 0 = ignore/inactive, 0.75 = active
    __shared__ float  s_rc[NWARP];
    __shared__ float  s_rr[NWARP];
    __shared__ int    s_rn[NWARP];
    __shared__ float  s_bl[2 * B_N];
    __shared__ bool   s_last;

    const int b    = blockIdx.y;
    const int tid  = threadIdx.x;
    const int lane = tid & 31;

    if (tid < M_N) {
        const float* g = gt + ((size_t)b * M_N + tid) * 5;
        float x1 = g[0], y1 = g[1], x2 = g[2], y2 = g[3], c = g[4];
        if (c < 0.0f) { x1 = y1 = x2 = y2 = 0.0f; }  // invalid gt never wins argmax
        s_gbox[tid]  = make_float4(x1, y1, x2, y2);
        s_garea[tid] = (x2 - x1) * (y2 - y1);
        s_gcls[tid]  = (int)c;
    }
    __syncthreads();

    const int a       = blockIdx.x * TPB + tid;
    const float* clsb = cls + (size_t)b * A_N * C_N;

    float flag = 0.0f;   // 0 or 0.75
    float accS = 0.0f;   // pos-class correction (fully weighted, log2 units)
    float accR = 0.0f;   // smooth-L1 sum
    int   npos = 0;

    // ---- Load anchor box (inactive lanes get an "empty" box that cannot
    //      extend the warp bbox) ----
    float4 ab = make_float4(3.0e38f, 3.0e38f, -3.0e38f, -3.0e38f);
    if (a < A_N) ab = *reinterpret_cast<const float4*>(anc + (size_t)a * 4);

    // ---- Warp bounding box over the 32 anchor boxes (butterfly reduce) ----
    float wx1 = ab.x, wy1 = ab.y, wx2 = ab.z, wy2 = ab.w;
    #pragma unroll
    for (int o = 16; o > 0; o >>= 1) {
        wx1 = fminf(wx1, __shfl_xor_sync(0xffffffffu, wx1, o));
        wy1 = fminf(wy1, __shfl_xor_sync(0xffffffffu, wy1, o));
        wx2 = fmaxf(wx2, __shfl_xor_sync(0xffffffffu, wx2, o));
        wy2 = fmaxf(wy2, __shfl_xor_sync(0xffffffffu, wy2, o));
    }

    // ---- Prune: gt m survives iff it intersects the warp bbox ----
    u64t mask;
    {
        const float4 g0 = s_gbox[lane];
        const float4 g1 = s_gbox[lane + 32];
        bool ov0 = (g0.x <= wx2) & (g0.z >= wx1) & (g0.y <= wy2) & (g0.w >= wy1);
        bool ov1 = (g1.x <= wx2) & (g1.z >= wx1) & (g1.y <= wy2) & (g1.w >= wy1);
        unsigned m0 = __ballot_sync(0xffffffffu, ov0);
        unsigned m1 = __ballot_sync(0xffffffffu, ov1);
        mask = (u64t)m0 | ((u64t)m1 << 32);
    }

    // ================= Phase 1: IoU argmax over surviving gts ==============
    if (a < A_N) {
        const float aw  = fabsf(ab.x - ab.z);
        const float ah  = fabsf(ab.y - ab.w);
        const float acx = ab.x + 0.5f * aw;
        const float acy = ab.y + 0.5f * ah;
        const float a_area = (ab.z - ab.x) * (ab.w - ab.y);

        // Packed-key argmax, SIGNED max:
        //   u = iw+|iw| = 2*max(iw,0) >= 0 ;  r = u*ih*rcp(S)  (<=0 if no overlap)
        //   key = (bits(r)&~63)|m ; r<0 -> negative key loses to any r>=0.
        int key0 = (int)0x80000000;
        u64t mk = mask;
        while (mk) {
            const int m = __ffsll((long long)mk) - 1;
            mk &= mk - 1;
            const float4 gb = s_gbox[m];
            float iw = fminf(ab.z, gb.z) - fmaxf(ab.x, gb.x);
            float ih = fminf(ab.w, gb.w) - fmaxf(ab.y, gb.y);
            float u  = iw + fabsf(iw);
            float r  = (u * ih) * rcp_fast(a_area + s_garea[m]);
            int kk = (int)((__float_as_uint(r) & 0xffffffc0u) | (unsigned)m);
            key0 = max(key0, kk);
        }
        const int bidx = key0 & 63;

        // Exact IoU of the winner for thresholding.
        // (If everything was pruned, bidx=0 and this anchor provably has
        //  inter=0 with gt 0 -> iou=0 -> neg, matching the reference.)
        const float4 gb = s_gbox[bidx];
        float iw = fmaxf(fminf(ab.z, gb.z) - fmaxf(ab.x, gb.x), 0.0f);
        float ih = fmaxf(fminf(ab.w, gb.w) - fmaxf(ab.y, gb.y), 0.0f);
        float inter = iw * ih;
        float un    = (a_area + s_garea[bidx]) - inter;
        float iou   = __fdividef(inter, un);
        const bool pos = (iou >= 0.5f);
        const bool neg = (iou < 0.4f);
        if (pos | neg) flag = 0.75f;

        if (pos) {
            float gw0 = gb.z - gb.x, gh0 = gb.w - gb.y;
            float gcx = gb.x + 0.5f * gw0, gcy = gb.y + 0.5f * gh0;
            float gw = fmaxf(gw0, 1.0f), gh = fmaxf(gh0, 1.0f);
            float tdx = __fdividef(gcx - acx, aw);
            float tdy = __fdividef(gcy - acy, ah);
            float tdh = __logf(__fdividef(gh, ah));
            float tdw = __logf(__fdividef(gw, aw));
            const float4 rg = *reinterpret_cast<const float4*>(reg + ((size_t)b * A_N + a) * 4);
            accR = smooth_l1(fabsf(tdx - rg.x)) + smooth_l1(fabsf(tdy - rg.y))
                 + smooth_l1(fabsf(tdh - rg.z)) + smooth_l1(fabsf(tdw - rg.w));
            npos = 1;
            // replace 0.75*base with the alpha-weighted positive term at (a,cid)
            const int cid = s_gcls[bidx];
            const float p = clsb[(size_t)a * C_N + cid];
            accS = pt(p) - 0.75f * bt(p);
        }
    }
    s_flag[tid] = flag;
    __syncwarp();

    // ====== Phase 2: flag-weighted focal stream (coalesced, branchless) ====
    const int sbase = tid & ~31;
    const int wbase = blockIdx.x * TPB + sbase;
    float accB0 = 0.0f, accB1 = 0.0f;

    if (wbase + 32 <= A_N) {
        // per-lane base pointer -> loads become immediate-offset LDGs
        const float4* tp = reinterpret_cast<const float4*>(
            clsb + (size_t)wbase * C_N) + lane;
        // flag index (lane+32k)/20 has period 5 in k: al(k)=alb[k%5]+8*(k/5)
        int alb[5];
        #pragma unroll
        for (int i = 0; i < 5; i++)
            alb[i] = (int)(((unsigned)lane + 32u * (unsigned)i) / 20u);

        #pragma unroll
        for (int k = 0; k < 20; k += 2) {
            const float fl0 = s_flag[sbase + alb[k % 5]       + 8 * (k / 5)];
            const float fl1 = s_flag[sbase + alb[(k + 1) % 5] + 8 * ((k + 1) / 5)];
            const float4 v0 = tp[32 * k];
            const float4 v1 = tp[32 * (k + 1)];
            accB0 = fmaf(fl0, bt4p(v0), accB0);
            accB1 = fmaf(fl1, bt4p(v1), accB1);
        }
    } else {
        // Tail (last x-block only): guarded
        const float4* wp = reinterpret_cast<const float4*>(clsb + (size_t)wbase * C_N);
        for (int k = 0; k < 20; k++) {
            const int f  = lane + 32 * k;
            const int al = f / 20;
            if (wbase + al < A_N) {
                const float fl = s_flag[sbase + al];
                accB0 = fmaf(fl, bt4p(wp[f]), accB0);
            }
        }
    }

    float accC = (accB0 + accB1) + accS;

    // ================= Block reduction -> per-block partials ===============
    #pragma unroll
    for (int o = 16; o > 0; o >>= 1) {
        accC += __shfl_down_sync(0xffffffffu, accC, o);
        accR += __shfl_down_sync(0xffffffffu, accR, o);
        npos += __shfl_down_sync(0xffffffffu, npos, o);
    }
    if (lane == 0) { s_rc[tid >> 5] = accC; s_rr[tid >> 5] = accR; s_rn[tid >> 5] = npos; }
    __syncthreads();

    const int blk = b * XBLK + blockIdx.x;
    if (tid == 0) {
        float c = 0.0f, r = 0.0f; int n = 0;
        #pragma unroll
        for (int w = 0; w < NWARP; w++) { c += s_rc[w]; r += s_rr[w]; n += s_rn[w]; }
        p_cls[blk] = c; p_reg[blk] = r; p_np[blk] = n;
        __threadfence();
        unsigned done = atomicAdd(&g_done, 1u);
        s_last = (done == NBLK - 1);
    }
    __syncthreads();

    // ================= Last block finalizes ================================
    if (s_last) {
        __threadfence();
        const int w = tid >> 5;
        if (w < B_N) {
            float c = 0.0f, r = 0.0f, n = 0.0f;
            for (int i = lane; i < XBLK; i += 32) {
                const int idx = w * XBLK + i;
                c += p_cls[idx]; r += p_reg[idx]; n += (float)p_np[idx];
            }
            #pragma unroll
            for (int o = 16; o > 0; o >>= 1) {
                c += __shfl_down_sync(0xffffffffu, c, o);
                r += __shfl_down_sync(0xffffffffu, r, o);
                n += __shfl_down_sync(0xffffffffu, n, o);
            }
            if (lane == 0) {
                const float NEG_LN2 = -0.69314718055994530942f;
                s_bl[w]       = NEG_LN2 * c / fmaxf(n, 1.0f);
                s_bl[B_N + w] = (n > 0.0f) ? r / (4.0f * n) : 0.0f;
            }
        }
        __syncthreads();
        if (tid == 0) {
            float cs = 0.0f, rs = 0.0f;
            #pragma unroll
            for (int i = 0; i < B_N; i++) { cs += s_bl[i]; rs += s_bl[B_N + i]; }
            out[0] = cs * (1.0f / (float)B_N);
            out[1] = rs * (1.0f / (float)B_N) * 50.0f;
            atomicExch(&g_done, 0u);   // reset for next graph replay
        }
    }
}

extern "C" void kernel_launch(void* const* d_in, const int* in_sizes, int n_in,
                              void* d_out, int out_size) {
    const float* regression     = (const float*)d_in[0];
    const float* classification = (const float*)d_in[1];
    const float* anchors        = (const float*)d_in[2];
    const float* gt_BB          = (const float*)d_in[3];
    float* out = (float*)d_out;

    dim3 grid(XBLK, B_N);
    fl_main_kernel<<<grid, TPB>>>(regression, classification, anchors, gt_BB, out);
}

// round 16
// speedup vs baseline: 1.3490x; 1.3490x over previous
#include <cuda_runtime.h>
#include <cuda_bf16.h>

#define A_N   49104
#define B_N   8
#define C_N   80
#define M_N   64
#define TPB   256
#define ABLK  512                        /* anchors per block (2 per thread) */
#define XBLK  ((A_N + ABLK - 1) / ABLK)  /* 96 */
#define NBLK  (XBLK * B_N)               /* 768 */
#define NWARP (TPB/32)

typedef unsigned long long u64t;

// Per-block partials (fully overwritten each launch before being read)
__device__ float    p_cls[NBLK];
__device__ float    p_reg[NBLK];
__device__ int      p_np[NBLK];
__device__ unsigned g_done = 0;         // reset by last block each launch

// ---------------- packed f32x2 helpers (Blackwell) ----------------
__device__ __forceinline__ u64t pk2(float a, float b) {
    u64t r; asm("mov.b64 %0, {%1, %2};" : "=l"(r) : "f"(a), "f"(b)); return r;
}
__device__ __forceinline__ void upk2(u64t v, float& a, float& b) {
    asm("mov.b64 {%0, %1}, %2;" : "=f"(a), "=f"(b) : "l"(v));
}
__device__ __forceinline__ u64t fma2(u64t a, u64t b, u64t c) {
    u64t d; asm("fma.rn.f32x2 %0, %1, %2, %3;" : "=l"(d) : "l"(a), "l"(b), "l"(c)); return d;
}
__device__ __forceinline__ u64t mul2(u64t a, u64t b) {
    u64t d; asm("mul.rn.f32x2 %0, %1, %2;" : "=l"(d) : "l"(a), "l"(b)); return d;
}
#define NEG1P 0xbf800000bf800000ull   /* (-1.f, -1.f) */
#define ONE1P 0x3f8000003f800000ull   /* ( 1.f,  1.f) */

__device__ __forceinline__ float rcp_fast(float x) {
    float y; asm("rcp.approx.f32 %0, %1;" : "=f"(y) : "f"(x)); return y;
}
__device__ __forceinline__ float smooth_l1(float d) {
    return (d <= (1.0f/9.0f)) ? 4.5f * d * d : d - (0.5f/9.0f);
}
__device__ __forceinline__ float bt(float p) {           // p^2*log2(1-p)
    return p * p * __log2f(1.0f - p);
}
__device__ __forceinline__ float pt(float p) {           // 0.25*(1-p)^2*log2(p)
    float q = 1.0f - p;
    return 0.25f * q * q * __log2f(p);
}
// Packed hot quad: sum of p^2*log2(1-p) over 4 elems (R13's proven fastest form)
__device__ __forceinline__ float bt4p(float4 v) {
    u64t v01 = pk2(v.x, v.y);
    u64t v23 = pk2(v.z, v.w);
    u64t q01 = fma2(v01, NEG1P, ONE1P);   // (1-p0, 1-p1)
    u64t q23 = fma2(v23, NEG1P, ONE1P);
    u64t s01 = mul2(v01, v01);            // (p0^2, p1^2)
    u64t s23 = mul2(v23, v23);
    float qa, qb, qc, qd, sa, sb, sc, sd;
    upk2(q01, qa, qb); upk2(q23, qc, qd);
    upk2(s01, sa, sb); upk2(s23, sc, sd);
    float l0 = __log2f(qa), l1 = __log2f(qb), l2 = __log2f(qc), l3 = __log2f(qd);
    float t  = sa * l0;
    t = fmaf(sb, l1, t);
    t = fmaf(sc, l2, t);
    t = fmaf(sd, l3, t);
    return t;
}

__global__ __launch_bounds__(TPB) void fl_main_kernel(
    const float* __restrict__ reg,    // [B, A, 4]
    const float* __restrict__ cls,    // [B, A, C]
    const float* __restrict__ anc,    // [1, A, 4]
    const float* __restrict__ gt,     // [B, M, 5]
    float* __restrict__ out)          // [2]
{
    __shared__ float4 s_gbox[M_N];
    __shared__ float  s_garea[M_N];
    __shared__ int    s_gcls[M_N];
    __shared__ float  s_flag[ABLK];   // 0 = ignore/inactive, 0.75 = active
    __shared__ float  s_rc[NWARP];
    __shared__ float  s_rr[NWARP];
    __shared__ int    s_rn[NWARP];
    __shared__ float  s_bl[2 * B_N];
    __shared__ bool   s_last;

    const int b    = blockIdx.y;
    const int tid  = threadIdx.x;
    const int lane = tid & 31;

    if (tid < M_N) {
        const float* g = gt + ((size_t)b * M_N + tid) * 5;
        float x1 = g[0], y1 = g[1], x2 = g[2], y2 = g[3], c = g[4];
        if (c < 0.0f) { x1 = y1 = x2 = y2 = 0.0f; }  // invalid gt never wins argmax
        s_gbox[tid]  = make_float4(x1, y1, x2, y2);
        s_garea[tid] = (x2 - x1) * (y2 - y1);
        s_gcls[tid]  = (int)c;
    }
    __syncthreads();

    const int base    = blockIdx.x * ABLK;
    const int a0      = base + tid;          // always < A_N (96*512 grid)
    const int a1      = base + 256 + tid;    // may exceed A_N in last block
    const float* clsb = cls + (size_t)b * A_N * C_N;

    float flag0 = 0.0f, flag1 = 0.0f;
    float accS = 0.0f;   // pos-class corrections (fully weighted, log2 units)
    float accR = 0.0f;   // smooth-L1 sum
    int   npos = 0;

    // Anchor boxes (invalid a1 -> sentinel "empty" box: provably iou=0 -> neg)
    const float4 ab0 = *reinterpret_cast<const float4*>(anc + (size_t)a0 * 4);
    float4 ab1 = make_float4(3.0e38f, 3.0e38f, -3.0e38f, -3.0e38f);
    if (a1 < A_N) ab1 = *reinterpret_cast<const float4*>(anc + (size_t)a1 * 4);

    const float aA0 = (ab0.z - ab0.x) * (ab0.w - ab0.y);
    const float aA1 = (ab1.z - ab1.x) * (ab1.w - ab1.y);

    // ================= Phase 1: IoU argmax, 2 anchors / thread =============
    // Packed across anchors: one fma2 -> (iw0, iw1), one -> (ih0, ih1).
    //   u = iw+|iw| = 2*max(iw,0) ; r = u*ih*rcp(S) (<=0 if no overlap)
    //   key = (bits(r)&~63)|m, SIGNED max; r<0 => negative key loses to r>=0.
    int key0 = (int)0x80000000, key1 = (int)0x80000000;
    #pragma unroll 8
    for (int m = 0; m < M_N; m++) {
        const float4 gb = s_gbox[m];
        const float  gS = s_garea[m];
        u64t mnx = pk2(fminf(ab0.z, gb.z), fminf(ab1.z, gb.z));
        u64t mxx = pk2(fmaxf(ab0.x, gb.x), fmaxf(ab1.x, gb.x));
        u64t mny = pk2(fminf(ab0.w, gb.w), fminf(ab1.w, gb.w));
        u64t mxy = pk2(fmaxf(ab0.y, gb.y), fmaxf(ab1.y, gb.y));
        u64t dw = fma2(mxx, NEG1P, mnx);    // (iw0, iw1)
        u64t dh = fma2(mxy, NEG1P, mny);    // (ih0, ih1)
        float iw0, iw1, ih0, ih1;
        upk2(dw, iw0, iw1); upk2(dh, ih0, ih1);
        float u0 = iw0 + fabsf(iw0);
        float u1 = iw1 + fabsf(iw1);
        float r0 = (u0 * ih0) * rcp_fast(aA0 + gS);
        float r1 = (u1 * ih1) * rcp_fast(aA1 + gS);
        int kk0 = (int)((__float_as_uint(r0) & 0xffffffc0u) | (unsigned)m);
        int kk1 = (int)((__float_as_uint(r1) & 0xffffffc0u) | (unsigned)m);
        key0 = max(key0, kk0);
        key1 = max(key1, kk1);
    }

    // ---- Per-anchor finalize (exact IoU re-eval for thresholds) ----
    #pragma unroll
    for (int s = 0; s < 2; s++) {
        const float4 ab  = s ? ab1 : ab0;
        const float  aA  = s ? aA1 : aA0;
        const int    a   = s ? a1  : a0;
        const int    bidx = (s ? key1 : key0) & 63;

        const float4 gb = s_gbox[bidx];
        float iw = fmaxf(fminf(ab.z, gb.z) - fmaxf(ab.x, gb.x), 0.0f);
        float ih = fmaxf(fminf(ab.w, gb.w) - fmaxf(ab.y, gb.y), 0.0f);
        float inter = iw * ih;
        float un    = (aA + s_garea[bidx]) - inter;
        float iou   = __fdividef(inter, un);
        const bool pos = (iou >= 0.5f);
        const bool neg = (iou < 0.4f);
        float fl = (pos | neg) ? 0.75f : 0.0f;
        if (s) flag1 = fl; else flag0 = fl;

        if (pos) {  // sentinel box can never be pos, so a < A_N here
            const float aw  = fabsf(ab.x - ab.z);
            const float ah  = fabsf(ab.y - ab.w);
            const float acx = ab.x + 0.5f * aw;
            const float acy = ab.y + 0.5f * ah;
            float gw0 = gb.z - gb.x, gh0 = gb.w - gb.y;
            float gcx = gb.x + 0.5f * gw0, gcy = gb.y + 0.5f * gh0;
            float gw = fmaxf(gw0, 1.0f), gh = fmaxf(gh0, 1.0f);
            float tdx = __fdividef(gcx - acx, aw);
            float tdy = __fdividef(gcy - acy, ah);
            float tdh = __logf(__fdividef(gh, ah));
            float tdw = __logf(__fdividef(gw, aw));
            const float4 rg = *reinterpret_cast<const float4*>(reg + ((size_t)b * A_N + a) * 4);
            accR += smooth_l1(fabsf(tdx - rg.x)) + smooth_l1(fabsf(tdy - rg.y))
                  + smooth_l1(fabsf(tdh - rg.z)) + smooth_l1(fabsf(tdw - rg.w));
            npos += 1;
            const int cid = s_gcls[bidx];
            const float p = clsb[(size_t)a * C_N + cid];
            accS += pt(p) - 0.75f * bt(p);
        }
    }
    s_flag[tid]       = flag0;
    s_flag[256 + tid] = flag1;
    __syncwarp();

    // ====== Phase 2: flag-weighted focal stream, two row groups ============
    const int sbase = tid & ~31;
    float accB0 = 0.0f, accB1 = 0.0f;

    // flag index (lane+32k)/20 has period 5 in k: al(k)=alb[k%5]+8*(k/5)
    int alb[5];
    #pragma unroll
    for (int i = 0; i < 5; i++)
        alb[i] = (int)(((unsigned)lane + 32u * (unsigned)i) / 20u);

    #pragma unroll
    for (int g = 0; g < 2; g++) {
        const int wbase = base + g * 256 + sbase;
        const int soff  = g * 256 + sbase;
        if (wbase + 32 <= A_N) {
            const float4* tp = reinterpret_cast<const float4*>(
                clsb + (size_t)wbase * C_N) + lane;
            #pragma unroll
            for (int k = 0; k < 20; k += 2) {
                const float fl0 = s_flag[soff + alb[k % 5]       + 8 * (k / 5)];
                const float fl1 = s_flag[soff + alb[(k + 1) % 5] + 8 * ((k + 1) / 5)];
                const float4 v0 = tp[32 * k];
                const float4 v1 = tp[32 * (k + 1)];
                accB0 = fmaf(fl0, bt4p(v0), accB0);
                accB1 = fmaf(fl1, bt4p(v1), accB1);
            }
        } else {
            // Tail (last x-block, second group only): guarded per quad
            const float4* wp = reinterpret_cast<const float4*>(
                clsb + (size_t)wbase * C_N);
            for (int k = 0; k < 20; k++) {
                const int f  = lane + 32 * k;
                const int al = f / 20;
                if (wbase + al < A_N) {
                    const float fl = s_flag[soff + al];
                    accB0 = fmaf(fl, bt4p(wp[f]), accB0);
                }
            }
        }
    }

    float accC = (accB0 + accB1) + accS;

    // ================= Block reduction -> per-block partials ===============
    #pragma unroll
    for (int o = 16; o > 0; o >>= 1) {
        accC += __shfl_down_sync(0xffffffffu, accC, o);
        accR += __shfl_down_sync(0xffffffffu, accR, o);
        npos += __shfl_down_sync(0xffffffffu, npos, o);
    }
    if (lane == 0) { s_rc[tid >> 5] = accC; s_rr[tid >> 5] = accR; s_rn[tid >> 5] = npos; }
    __syncthreads();

    const int blk = b * XBLK + blockIdx.x;
    if (tid == 0) {
        float c = 0.0f, r = 0.0f; int n = 0;
        #pragma unroll
        for (int w = 0; w < NWARP; w++) { c += s_rc[w]; r += s_rr[w]; n += s_rn[w]; }
        p_cls[blk] = c; p_reg[blk] = r; p_np[blk] = n;
        __threadfence();
        unsigned done = atomicAdd(&g_done, 1u);
        s_last = (done == NBLK - 1);
    }
    __syncthreads();

    // ================= Last block finalizes ================================
    if (s_last) {
        __threadfence();
        const int w = tid >> 5;
        if (w < B_N) {
            float c = 0.0f, r = 0.0f, n = 0.0f;
            for (int i = lane; i < XBLK; i += 32) {
                const int idx = w * XBLK + i;
                c += p_cls[idx]; r += p_reg[idx]; n += (float)p_np[idx];
            }
            #pragma unroll
            for (int o = 16; o > 0; o >>= 1) {
                c += __shfl_down_sync(0xffffffffu, c, o);
                r += __shfl_down_sync(0xffffffffu, r, o);
                n += __shfl_down_sync(0xffffffffu, n, o);
            }
            if (lane == 0) {
                const float NEG_LN2 = -0.69314718055994530942f;
                s_bl[w]       = NEG_LN2 * c / fmaxf(n, 1.0f);
                s_bl[B_N + w] = (n > 0.0f) ? r / (4.0f * n) : 0.0f;
            }
        }
        __syncthreads();
        if (tid == 0) {
            float cs = 0.0f, rs = 0.0f;
            #pragma unroll
            for (int i = 0; i < B_N; i++) { cs += s_bl[i]; rs += s_bl[B_N + i]; }
            out[0] = cs * (1.0f / (float)B_N);
            out[1] = rs * (1.0f / (float)B_N) * 50.0f;
            atomicExch(&g_done, 0u);   // reset for next graph replay
        }
    }
}

extern "C" void kernel_launch(void* const* d_in, const int* in_sizes, int n_in,
                              void* d_out, int out_size) {
    const float* regression     = (const float*)d_in[0];
    const float* classification = (const float*)d_in[1];
    const float* anchors        = (const float*)d_in[2];
    const float* gt_BB          = (const float*)d_in[3];
    float* out = (float*)d_out;

    dim3 grid(XBLK, B_N);
    fl_main_kernel<<<grid, TPB>>>(regression, classification, anchors, gt_BB, out);
}

// round 17
// speedup vs baseline: 1.4207x; 1.0531x over previous
#include <cuda_runtime.h>
#include <cuda_bf16.h>

#define A_N   49104
#define B_N   8
#define C_N   80
#define M_N   64
#define TPB   256
#define ABLK  768                        /* anchors per block (3 per thread) */
#define XBLK  64                         /* 64*768 = 49152 >= A_N */
#define NBLK  (XBLK * B_N)               /* 512 */
#define NWARP (TPB/32)

typedef unsigned long long u64t;

// Per-block partials (fully overwritten each launch before being read)
__device__ float    p_cls[NBLK];
__device__ float    p_reg[NBLK];
__device__ int      p_np[NBLK];
__device__ unsigned g_done = 0;         // reset by last block each launch

// ---------------- packed f32x2 helpers (Blackwell) ----------------
__device__ __forceinline__ u64t pk2(float a, float b) {
    u64t r; asm("mov.b64 %0, {%1, %2};" : "=l"(r) : "f"(a), "f"(b)); return r;
}
__device__ __forceinline__ void upk2(u64t v, float& a, float& b) {
    asm("mov.b64 {%0, %1}, %2;" : "=f"(a), "=f"(b) : "l"(v));
}
__device__ __forceinline__ u64t fma2(u64t a, u64t b, u64t c) {
    u64t d; asm("fma.rn.f32x2 %0, %1, %2, %3;" : "=l"(d) : "l"(a), "l"(b), "l"(c)); return d;
}
__device__ __forceinline__ u64t mul2(u64t a, u64t b) {
    u64t d; asm("mul.rn.f32x2 %0, %1, %2;" : "=l"(d) : "l"(a), "l"(b)); return d;
}
#define NEG1P 0xbf800000bf800000ull   /* (-1.f, -1.f) */
#define ONE1P 0x3f8000003f800000ull   /* ( 1.f,  1.f) */

__device__ __forceinline__ float rcp_fast(float x) {
    float y; asm("rcp.approx.f32 %0, %1;" : "=f"(y) : "f"(x)); return y;
}
__device__ __forceinline__ float smooth_l1(float d) {
    return (d <= (1.0f/9.0f)) ? 4.5f * d * d : d - (0.5f/9.0f);
}
__device__ __forceinline__ float bt(float p) {           // p^2*log2(1-p)
    return p * p * __log2f(1.0f - p);
}
__device__ __forceinline__ float pt(float p) {           // 0.25*(1-p)^2*log2(p)
    float q = 1.0f - p;
    return 0.25f * q * q * __log2f(p);
}
// Packed hot quad: sum of p^2*log2(1-p) over 4 elems (R13's proven fastest form)
__device__ __forceinline__ float bt4p(float4 v) {
    u64t v01 = pk2(v.x, v.y);
    u64t v23 = pk2(v.z, v.w);
    u64t q01 = fma2(v01, NEG1P, ONE1P);   // (1-p0, 1-p1)
    u64t q23 = fma2(v23, NEG1P, ONE1P);
    u64t s01 = mul2(v01, v01);            // (p0^2, p1^2)
    u64t s23 = mul2(v23, v23);
    float qa, qb, qc, qd, sa, sb, sc, sd;
    upk2(q01, qa, qb); upk2(q23, qc, qd);
    upk2(s01, sa, sb); upk2(s23, sc, sd);
    float l0 = __log2f(qa), l1 = __log2f(qb), l2 = __log2f(qc), l3 = __log2f(qd);
    float t  = sa * l0;
    t = fmaf(sb, l1, t);
    t = fmaf(sc, l2, t);
    t = fmaf(sd, l3, t);
    return t;
}

__global__ __launch_bounds__(TPB, 4) void fl_main_kernel(
    const float* __restrict__ reg,    // [B, A, 4]
    const float* __restrict__ cls,    // [B, A, C]
    const float* __restrict__ anc,    // [1, A, 4]
    const float* __restrict__ gt,     // [B, M, 5]
    float* __restrict__ out)          // [2]
{
    __shared__ float4 s_gbox[M_N];
    __shared__ float  s_garea[M_N];
    __shared__ int    s_gcls[M_N];
    __shared__ float  s_flag[ABLK];   // 0 = ignore/inactive, 0.75 = active
    __shared__ float  s_rc[NWARP];
    __shared__ float  s_rr[NWARP];
    __shared__ int    s_rn[NWARP];
    __shared__ float  s_bl[2 * B_N];
    __shared__ bool   s_last;

    const int b    = blockIdx.y;
    const int tid  = threadIdx.x;
    const int lane = tid & 31;

    if (tid < M_N) {
        const float* g = gt + ((size_t)b * M_N + tid) * 5;
        float x1 = g[0], y1 = g[1], x2 = g[2], y2 = g[3], c = g[4];
        if (c < 0.0f) { x1 = y1 = x2 = y2 = 0.0f; }  // invalid gt never wins argmax
        s_gbox[tid]  = make_float4(x1, y1, x2, y2);
        s_garea[tid] = (x2 - x1) * (y2 - y1);
        s_gcls[tid]  = (int)c;
    }
    __syncthreads();

    const int base    = blockIdx.x * ABLK;
    const int a0      = base + tid;          // < A_N always (48384+255 max)
    const int a1      = base + 256 + tid;    // < A_N always (48640+255 max)
    const int a2      = base + 512 + tid;    // may exceed A_N in last block
    const float* clsb = cls + (size_t)b * A_N * C_N;

    float accS = 0.0f;   // pos-class corrections (fully weighted, log2 units)
    float accR = 0.0f;   // smooth-L1 sum
    int   npos = 0;

    // Anchor boxes (invalid a2 -> sentinel "empty" box: iou=0 -> neg, flag=0.75
    //  but its row is never read in phase 2 tail, and it can't be pos)
    const float4 ab0 = *reinterpret_cast<const float4*>(anc + (size_t)a0 * 4);
    const float4 ab1 = *reinterpret_cast<const float4*>(anc + (size_t)a1 * 4);
    float4 ab2 = make_float4(3.0e38f, 3.0e38f, -3.0e38f, -3.0e38f);
    if (a2 < A_N) ab2 = *reinterpret_cast<const float4*>(anc + (size_t)a2 * 4);

    const float aA0 = (ab0.z - ab0.x) * (ab0.w - ab0.y);
    const float aA1 = (ab1.z - ab1.x) * (ab1.w - ab1.y);
    const float aA2 = (ab2.z - ab2.x) * (ab2.w - ab2.y);

    // ================= Phase 1: IoU argmax, 3 anchors / thread =============
    // Anchors 0,1 packed across the pair (one fma2 -> (iw0,iw1), one -> (ih0,ih1));
    // anchor 2 scalar. u = iw+|iw| = 2*max(iw,0); r = u*ih*rcp(S) (<=0 if no overlap)
    // key = (bits(r)&~63)|m, SIGNED max; r<0 -> negative key loses to any r>=0.
    int key0 = (int)0x80000000, key1 = (int)0x80000000, key2 = (int)0x80000000;
    #pragma unroll 8
    for (int m = 0; m < M_N; m++) {
        const float4 gb = s_gbox[m];
        const float  gS = s_garea[m];
        // packed pair (a0, a1)
        u64t mnx = pk2(fminf(ab0.z, gb.z), fminf(ab1.z, gb.z));
        u64t mxx = pk2(fmaxf(ab0.x, gb.x), fmaxf(ab1.x, gb.x));
        u64t mny = pk2(fminf(ab0.w, gb.w), fminf(ab1.w, gb.w));
        u64t mxy = pk2(fmaxf(ab0.y, gb.y), fmaxf(ab1.y, gb.y));
        u64t dw = fma2(mxx, NEG1P, mnx);    // (iw0, iw1)
        u64t dh = fma2(mxy, NEG1P, mny);    // (ih0, ih1)
        float iw0, iw1, ih0, ih1;
        upk2(dw, iw0, iw1); upk2(dh, ih0, ih1);
        float u0 = iw0 + fabsf(iw0);
        float u1 = iw1 + fabsf(iw1);
        float r0 = (u0 * ih0) * rcp_fast(aA0 + gS);
        float r1 = (u1 * ih1) * rcp_fast(aA1 + gS);
        int kk0 = (int)((__float_as_uint(r0) & 0xffffffc0u) | (unsigned)m);
        int kk1 = (int)((__float_as_uint(r1) & 0xffffffc0u) | (unsigned)m);
        key0 = max(key0, kk0);
        key1 = max(key1, kk1);
        // scalar third anchor
        float iw2 = fminf(ab2.z, gb.z) - fmaxf(ab2.x, gb.x);
        float ih2 = fminf(ab2.w, gb.w) - fmaxf(ab2.y, gb.y);
        float u2  = iw2 + fabsf(iw2);
        float r2  = (u2 * ih2) * rcp_fast(aA2 + gS);
        int kk2 = (int)((__float_as_uint(r2) & 0xffffffc0u) | (unsigned)m);
        key2 = max(key2, kk2);
    }

    // ---- Per-anchor finalize (exact IoU re-eval for thresholds) ----
    #pragma unroll
    for (int s = 0; s < 3; s++) {
        const float4 ab  = (s == 0) ? ab0 : (s == 1) ? ab1 : ab2;
        const float  aA  = (s == 0) ? aA0 : (s == 1) ? aA1 : aA2;
        const int    a   = (s == 0) ? a0  : (s == 1) ? a1  : a2;
        const int    bidx = ((s == 0) ? key0 : (s == 1) ? key1 : key2) & 63;

        const float4 gb = s_gbox[bidx];
        float iw = fmaxf(fminf(ab.z, gb.z) - fmaxf(ab.x, gb.x), 0.0f);
        float ih = fmaxf(fminf(ab.w, gb.w) - fmaxf(ab.y, gb.y), 0.0f);
        float inter = iw * ih;
        float un    = (aA + s_garea[bidx]) - inter;
        float iou   = __fdividef(inter, un);
        const bool pos = (iou >= 0.5f);
        const bool neg = (iou < 0.4f);
        s_flag[s * 256 + tid] = (pos | neg) ? 0.75f : 0.0f;

        if (pos) {  // sentinel box can never be pos, so a < A_N here
            const float aw  = fabsf(ab.x - ab.z);
            const float ah  = fabsf(ab.y - ab.w);
            const float acx = ab.x + 0.5f * aw;
            const float acy = ab.y + 0.5f * ah;
            float gw0 = gb.z - gb.x, gh0 = gb.w - gb.y;
            float gcx = gb.x + 0.5f * gw0, gcy = gb.y + 0.5f * gh0;
            float gw = fmaxf(gw0, 1.0f), gh = fmaxf(gh0, 1.0f);
            float tdx = __fdividef(gcx - acx, aw);
            float tdy = __fdividef(gcy - acy, ah);
            float tdh = __logf(__fdividef(gh, ah));
            float tdw = __logf(__fdividef(gw, aw));
            const float4 rg = *reinterpret_cast<const float4*>(reg + ((size_t)b * A_N + a) * 4);
            accR += smooth_l1(fabsf(tdx - rg.x)) + smooth_l1(fabsf(tdy - rg.y))
                  + smooth_l1(fabsf(tdh - rg.z)) + smooth_l1(fabsf(tdw - rg.w));
            npos += 1;
            const int cid = s_gcls[bidx];
            const float p = clsb[(size_t)a * C_N + cid];
            accS += pt(p) - 0.75f * bt(p);
        }
    }
    __syncwarp();

    // ====== Phase 2: flag-weighted focal stream, three row groups ==========
    const int sbase = tid & ~31;
    float accB0 = 0.0f, accB1 = 0.0f;

    // flag index (lane+32k)/20 has period 5 in k: al(k)=alb[k%5]+8*(k/5)
    int alb[5];
    #pragma unroll
    for (int i = 0; i < 5; i++)
        alb[i] = (int)(((unsigned)lane + 32u * (unsigned)i) / 20u);

    #pragma unroll
    for (int g = 0; g < 3; g++) {
        const int wbase = base + g * 256 + sbase;
        const int soff  = g * 256 + sbase;
        if (wbase + 32 <= A_N) {
            const float4* tp = reinterpret_cast<const float4*>(
                clsb + (size_t)wbase * C_N) + lane;
            #pragma unroll
            for (int k = 0; k < 20; k += 2) {
                const float fl0 = s_flag[soff + alb[k % 5]       + 8 * (k / 5)];
                const float fl1 = s_flag[soff + alb[(k + 1) % 5] + 8 * ((k + 1) / 5)];
                const float4 v0 = tp[32 * k];
                const float4 v1 = tp[32 * (k + 1)];
                accB0 = fmaf(fl0, bt4p(v0), accB0);
                accB1 = fmaf(fl1, bt4p(v1), accB1);
            }
        } else if (wbase < A_N) {
            // Tail (last x-block, third group only): guarded per quad
            const float4* wp = reinterpret_cast<const float4*>(
                clsb + (size_t)wbase * C_N);
            for (int k = 0; k < 20; k++) {
                const int f  = lane + 32 * k;
                const int al = f / 20;
                if (wbase + al < A_N) {
                    const float fl = s_flag[soff + al];
                    accB0 = fmaf(fl, bt4p(wp[f]), accB0);
                }
            }
        }
    }

    float accC = (accB0 + accB1) + accS;

    // ================= Block reduction -> per-block partials ===============
    #pragma unroll
    for (int o = 16; o > 0; o >>= 1) {
        accC += __shfl_down_sync(0xffffffffu, accC, o);
        accR += __shfl_down_sync(0xffffffffu, accR, o);
        npos += __shfl_down_sync(0xffffffffu, npos, o);
    }
    if (lane == 0) { s_rc[tid >> 5] = accC; s_rr[tid >> 5] = accR; s_rn[tid >> 5] = npos; }
    __syncthreads();

    const int blk = b * XBLK + blockIdx.x;
    if (tid == 0) {
        float c = 0.0f, r = 0.0f; int n = 0;
        #pragma unroll
        for (int w = 0; w < NWARP; w++) { c += s_rc[w]; r += s_rr[w]; n += s_rn[w]; }
        p_cls[blk] = c; p_reg[blk] = r; p_np[blk] = n;
        __threadfence();
        unsigned done = atomicAdd(&g_done, 1u);
        s_last = (done == NBLK - 1);
    }
    __syncthreads();

    // ================= Last block finalizes ================================
    if (s_last) {
        __threadfence();
        const int w = tid >> 5;
        if (w < B_N) {
            float c = 0.0f, r = 0.0f, n = 0.0f;
            for (int i = lane; i < XBLK; i += 32) {
                const int idx = w * XBLK + i;
                c += p_cls[idx]; r += p_reg[idx]; n += (float)p_np[idx];
            }
            #pragma unroll
            for (int o = 16; o > 0; o >>= 1) {
                c += __shfl_down_sync(0xffffffffu, c, o);
                r += __shfl_down_sync(0xffffffffu, r, o);
                n += __shfl_down_sync(0xffffffffu, n, o);
            }
            if (lane == 0) {
                const float NEG_LN2 = -0.69314718055994530942f;
                s_bl[w]       = NEG_LN2 * c / fmaxf(n, 1.0f);
                s_bl[B_N + w] = (n > 0.0f) ? r / (4.0f * n) : 0.0f;
            }
        }
        __syncthreads();
        if (tid == 0) {
            float cs = 0.0f, rs = 0.0f;
            #pragma unroll
            for (int i = 0; i < B_N; i++) { cs += s_bl[i]; rs += s_bl[B_N + i]; }
            out[0] = cs * (1.0f / (float)B_N);
            out[1] = rs * (1.0f / (float)B_N) * 50.0f;
            atomicExch(&g_done, 0u);   // reset for next graph replay
        }
    }
}

extern "C" void kernel_launch(void* const* d_in, const int* in_sizes, int n_in,
                              void* d_out, int out_size) {
    const float* regression     = (const float*)d_in[0];
    const float* classification = (const float*)d_in[1];
    const float* anchors        = (const float*)d_in[2];
    const float* gt_BB          = (const float*)d_in[3];
    float* out = (float*)d_out;

    dim3 grid(XBLK, B_N);
    fl_main_kernel<<<grid, TPB>>>(regression, classification, anchors, gt_BB, out);
}